// round 12
// baseline (speedup 1.0000x reference)
#include <cuda_runtime.h>
#include <cuda_bf16.h>
#include <cuda_fp16.h>
#include <cstdint>

#define B_    8
#define C_    256
#define N_    1024
#define NH    8
#define HD    32
#define R_    4
#define MTOT  776
#define PR_   768
#define SCALE 0.17677669529663689f
#define LOG2E 1.4426950408889634f

// ---------------- scratch ----------------
__device__ float g_vf[B_ * C_ * N_];          // v projection fp32 (shortcut blend)
__device__ float g_sq[B_ * N_];
__device__ float g_sk[B_ * N_];
__device__ float g_ball[MTOT];
__device__ __half g_wh[MTOT * C_];            // stacked W (fp16): q,k,v,gq,gk rows
__device__ __half g_wph[C_ * C_];             // Wp (fp16)
__device__ __half g_xh[B_ * C_ * N_];         // x (fp16)
__device__ __nv_bfloat16 g_qB[B_ * C_ * N_];  // gated*SCALE*LOG2E
__device__ __nv_bfloat16 g_kB[B_ * C_ * N_];  // gated
__device__ __nv_bfloat16 g_vB[B_ * C_ * N_];
__device__ __half g_gh[B_ * C_ * N_];         // gated output (fp16, gemm2 input)

// ---------------- ptx helpers ----------------
__device__ __forceinline__ void cp16(void* d, const void* s) {
    uint32_t ds = (uint32_t)__cvta_generic_to_shared(d);
    asm volatile("cp.async.cg.shared.global [%0], [%1], 16;" :: "r"(ds), "l"(s));
}
__device__ __forceinline__ void cp_commit() { asm volatile("cp.async.commit_group;"); }

__device__ __forceinline__ void ldsm_x4(uint32_t (&r)[4], const void* p) {
    uint32_t a = (uint32_t)__cvta_generic_to_shared(p);
    asm volatile("ldmatrix.sync.aligned.m8n8.x4.shared.b16 {%0,%1,%2,%3},[%4];"
                 : "=r"(r[0]), "=r"(r[1]), "=r"(r[2]), "=r"(r[3]) : "r"(a));
}
__device__ __forceinline__ void ldsm_x4t(uint32_t (&r)[4], const void* p) {
    uint32_t a = (uint32_t)__cvta_generic_to_shared(p);
    asm volatile("ldmatrix.sync.aligned.m8n8.x4.trans.shared.b16 {%0,%1,%2,%3},[%4];"
                 : "=r"(r[0]), "=r"(r[1]), "=r"(r[2]), "=r"(r[3]) : "r"(a));
}
__device__ __forceinline__ void ldsm_x2(uint32_t (&r)[2], const void* p) {
    uint32_t a = (uint32_t)__cvta_generic_to_shared(p);
    asm volatile("ldmatrix.sync.aligned.m8n8.x2.shared.b16 {%0,%1},[%2];"
                 : "=r"(r[0]), "=r"(r[1]) : "r"(a));
}
__device__ __forceinline__ void ldsm_x2t(uint32_t (&r)[2], const void* p) {
    uint32_t a = (uint32_t)__cvta_generic_to_shared(p);
    asm volatile("ldmatrix.sync.aligned.m8n8.x2.trans.shared.b16 {%0,%1},[%2];"
                 : "=r"(r[0]), "=r"(r[1]) : "r"(a));
}
__device__ __forceinline__ void mma16816(float (&d)[4], const uint32_t (&a)[4], const uint32_t (&b)[2]) {
    asm volatile(
        "mma.sync.aligned.m16n8k16.row.col.f32.bf16.bf16.f32 "
        "{%0,%1,%2,%3},{%4,%5,%6,%7},{%8,%9},{%0,%1,%2,%3};"
        : "+f"(d[0]), "+f"(d[1]), "+f"(d[2]), "+f"(d[3])
        : "r"(a[0]), "r"(a[1]), "r"(a[2]), "r"(a[3]), "r"(b[0]), "r"(b[1]));
}
__device__ __forceinline__ void mmah16816(float (&d)[4], const uint32_t (&a)[4], const uint32_t (&b)[2]) {
    asm volatile(
        "mma.sync.aligned.m16n8k16.row.col.f32.f16.f16.f32 "
        "{%0,%1,%2,%3},{%4,%5,%6,%7},{%8,%9},{%0,%1,%2,%3};"
        : "+f"(d[0]), "+f"(d[1]), "+f"(d[2]), "+f"(d[3])
        : "r"(a[0]), "r"(a[1]), "r"(a[2]), "r"(a[3]), "r"(b[0]), "r"(b[1]));
}
__device__ __forceinline__ uint32_t packbf(float lo, float hi) {
    __nv_bfloat162 t = __floats2bfloat162_rn(lo, hi);
    return *reinterpret_cast<uint32_t*>(&t);
}
__device__ __forceinline__ uint32_t cvt2bf(float hi, float lo) {
    uint32_t y; asm("cvt.rn.bf16x2.f32 %0, %1, %2;" : "=r"(y) : "f"(hi), "f"(lo)); return y;
}
__device__ __forceinline__ uint32_t ex2_bf16x2(uint32_t x) {
    uint32_t y; asm("ex2.approx.ftz.bf16x2 %0, %1;" : "=r"(y) : "r"(x)); return y;
}

// ---------------- assemble weights -> fp16 ----------------
__global__ void assemble_kernel(
    const float* __restrict__ Wq, const float* __restrict__ bq,
    const float* __restrict__ Wk, const float* __restrict__ bk,
    const float* __restrict__ Wv, const float* __restrict__ bv,
    const float* __restrict__ Wsq, const float* __restrict__ bsq,
    const float* __restrict__ Wsk, const float* __restrict__ bsk,
    const float* __restrict__ Wp)
{
    int o = blockIdx.x;
    int k = threadIdx.x;
    if (o < MTOT) {
        const float* src; const float* bs; int r;
        if (o < 256)      { src = Wq  + o * 256;       bs = bq;  r = o; }
        else if (o < 512) { src = Wk  + (o-256) * 256; bs = bk;  r = o - 256; }
        else if (o < 768) { src = Wv  + (o-512) * 256; bs = bv;  r = o - 512; }
        else if (o < 772) { src = Wsq + (o-768) * 256; bs = bsq; r = o - 768; }
        else              { src = Wsk + (o-772) * 256; bs = bsk; r = o - 772; }
        g_wh[o * 256 + k] = __float2half_rn(src[k]);
        if (k == 0) g_ball[o] = bs[r];
    } else {
        int r = o - MTOT;
        g_wph[r * 256 + k] = __float2half_rn(Wp[r * 256 + k]);
    }
}

// ---------------- x -> fp16 (float4) ----------------
__global__ void xcvt_kernel(const float* __restrict__ x) {
    int i = (blockIdx.x * 256 + threadIdx.x) * 4;
    float4 v = *reinterpret_cast<const float4*>(x + i);
    __half2 p0 = __floats2half2_rn(v.x, v.y);
    __half2 p1 = __floats2half2_rn(v.z, v.w);
    uint2 o;
    o.x = *reinterpret_cast<uint32_t*>(&p0);
    o.y = *reinterpret_cast<uint32_t*>(&p1);
    *reinterpret_cast<uint2*>(g_xh + i) = o;
}

// ---------------- fp16 GEMM, templated epilogue ----------------
// MODE 0: plain fp32 Y write (gemm2)
// MODE 1: fused qkv convert (gemm1): per-tile category q/k/v, writes bf16 (+v fp32)
// MODE 2: gate GEMM: 8 valid A rows, epilogue = gumbel softmax -> g_sq/g_sk
#define ASTR 24
template<int MODE>
__global__ __launch_bounds__(256) void gemmh_kernel(
    const __half* __restrict__ W, const float* __restrict__ bias,
    const __half* __restrict__ X, float* __restrict__ Y,
    int Ma, long xStride, long yStride,
    const float* __restrict__ gq, const float* __restrict__ gk)
{
    int b  = blockIdx.z;
    int m0 = blockIdx.y * 128;
    int n0 = blockIdx.x * 128;
    const __half* XB = X + (long)b * xStride;

    __shared__ __align__(16) __half sA[2][128 * ASTR];
    __shared__ __align__(16) __half sB[2][16 * 136];
    __shared__ float sg[8][132];

    int tid  = threadIdx.x;
    int warp = tid >> 5, lane = tid & 31;
    int wm = warp >> 2, wn = warp & 3;
    int g = lane >> 2, t = lane & 3;

    float acc[4][4][4];
    #pragma unroll
    for (int mi = 0; mi < 4; mi++)
        #pragma unroll
        for (int ni = 0; ni < 4; ni++)
            #pragma unroll
            for (int r = 0; r < 4; r++) acc[mi][ni][r] = 0.f;

    auto loadStage = [&](int step, int s) {
        int k0 = step * 16;
        {
            int row = tid >> 1, half = tid & 1;
            int gm = m0 + row;
            __half* d = &sA[s][row * ASTR + half * 8];
            if (gm < Ma) cp16(d, W + gm * 256 + k0 + half * 8);
            else         *reinterpret_cast<uint4*>(d) = make_uint4(0,0,0,0);
        }
        {
            int row = tid >> 4, seg = tid & 15;
            cp16(&sB[s][row * 136 + seg * 8], XB + (long)(k0 + row) * N_ + n0 + seg * 8);
        }
        cp_commit();
    };

    loadStage(0, 0);
    for (int step = 0; step < 16; step++) {
        int s = step & 1;
        if (step < 15) {
            loadStage(step + 1, s ^ 1);
            asm volatile("cp.async.wait_group 1;");
        } else {
            asm volatile("cp.async.wait_group 0;");
        }
        __syncthreads();

        uint32_t afr[4][4];
        #pragma unroll
        for (int mi = 0; mi < 4; mi++) {
            const __half* p = &sA[s][(wm * 64 + mi * 16 + (lane & 15)) * ASTR] + ((lane >> 4) & 1) * 8;
            ldsm_x4(afr[mi], p);
        }
        uint32_t bfr[4][2];
        #pragma unroll
        for (int ni = 0; ni < 4; ni++) {
            const __half* p = &sB[s][(lane & 15) * 136 + wn * 32 + ni * 8];
            ldsm_x2t(bfr[ni], p);
        }
        #pragma unroll
        for (int mi = 0; mi < 4; mi++)
            #pragma unroll
            for (int ni = 0; ni < 4; ni++)
                mmah16816(acc[mi][ni], afr[mi], bfr[ni]);
        __syncthreads();
    }

    if (MODE == 0) {
        float* Yb = Y + (long)b * yStride;
        #pragma unroll
        for (int mi = 0; mi < 4; mi++) {
            int r0 = m0 + wm * 64 + mi * 16 + g;
            int r1 = r0 + 8;
            float bv0 = bias[r0], bv1 = bias[r1];
            #pragma unroll
            for (int ni = 0; ni < 4; ni++) {
                int col = n0 + wn * 32 + ni * 8 + 2 * t;
                Yb[(long)r0 * N_ + col]     = acc[mi][ni][0] + bv0;
                Yb[(long)r0 * N_ + col + 1] = acc[mi][ni][1] + bv0;
                Yb[(long)r1 * N_ + col]     = acc[mi][ni][2] + bv1;
                Yb[(long)r1 * N_ + col + 1] = acc[mi][ni][3] + bv1;
            }
        }
    } else if (MODE == 1) {
        // fused convert: category uniform per block (q: m0<256, k: <512, v: <768)
        const float QMUL = SCALE * LOG2E;
        int cat = m0 >> 8;
        const float* sqb = g_sq + (long)b * N_;
        const float* skb = g_sk + (long)b * N_;
        #pragma unroll
        for (int mi = 0; mi < 4; mi++) {
            int gr0 = m0 + wm * 64 + mi * 16 + g;
            int rr0 = gr0 & 255, rr1 = rr0 + 8;
            float bv0 = bias[gr0], bv1 = bias[gr0 + 8];
            long o0 = ((long)b * C_ + rr0) * N_;
            long o1 = ((long)b * C_ + rr1) * N_;
            #pragma unroll
            for (int ni = 0; ni < 4; ni++) {
                int col = n0 + wn * 32 + ni * 8 + 2 * t;
                float a0 = acc[mi][ni][0] + bv0, a1 = acc[mi][ni][1] + bv0;
                float a2 = acc[mi][ni][2] + bv1, a3 = acc[mi][ni][3] + bv1;
                if (cat == 0) {
                    float2 s = *reinterpret_cast<const float2*>(sqb + col);
                    *reinterpret_cast<uint32_t*>(g_qB + o0 + col) = packbf(a0 * s.x * QMUL, a1 * s.y * QMUL);
                    *reinterpret_cast<uint32_t*>(g_qB + o1 + col) = packbf(a2 * s.x * QMUL, a3 * s.y * QMUL);
                } else if (cat == 1) {
                    float2 s = *reinterpret_cast<const float2*>(skb + col);
                    *reinterpret_cast<uint32_t*>(g_kB + o0 + col) = packbf(a0 * s.x, a1 * s.y);
                    *reinterpret_cast<uint32_t*>(g_kB + o1 + col) = packbf(a2 * s.x, a3 * s.y);
                } else {
                    *reinterpret_cast<uint32_t*>(g_vB + o0 + col) = packbf(a0, a1);
                    *reinterpret_cast<uint32_t*>(g_vB + o1 + col) = packbf(a2, a3);
                    *reinterpret_cast<float2*>(g_vf + o0 + col) = make_float2(a0, a1);
                    *reinterpret_cast<float2*>(g_vf + o1 + col) = make_float2(a2, a3);
                }
            }
        }
    } else {
        // gate softmax: valid rows 0-7 live in wm==0, mi==0 accumulators
        if (wm == 0) {
            float bv = bias[g];   // bias pointer pre-offset to gate rows
            #pragma unroll
            for (int ni = 0; ni < 4; ni++) {
                int col = wn * 32 + ni * 8 + 2 * t;
                sg[g][col]     = acc[0][ni][0] + bv;
                sg[g][col + 1] = acc[0][ni][1] + bv;
            }
        }
        __syncthreads();
        if (tid < 128) {
            int n = n0 + tid;
            float lq[4], lk[4];
            #pragma unroll
            for (int r = 0; r < 4; r++) {
                lq[r] = sg[r][tid]     + gq[(b * R_ + r) * N_ + n];
                lk[r] = sg[4 + r][tid] + gk[(b * R_ + r) * N_ + n];
            }
            float mq = fmaxf(fmaxf(lq[0], lq[1]), fmaxf(lq[2], lq[3]));
            float s2 = 0.f;
            #pragma unroll
            for (int r = 0; r < 4; r++) s2 += __expf(lq[r] - mq);
            g_sq[b * N_ + n] = __expf(lq[0] - mq) / s2;
            float mk = fmaxf(fmaxf(lk[0], lk[1]), fmaxf(lk[2], lk[3]));
            s2 = 0.f;
            #pragma unroll
            for (int r = 0; r < 4; r++) s2 += __expf(lk[r] - mk);
            g_sk[b * N_ + n] = __expf(lk[0] - mk) / s2;
        }
    }
}

// ---------------- flash attention: bf16x2 exp + ones-MMA row sums ----------------
#define QSTR 136
#define KSTR 72
__global__ __launch_bounds__(256) void attn_kernel() {
    int b = blockIdx.z, h = blockIdx.y;
    int n0 = blockIdx.x * 128;
    const __nv_bfloat16* qBp = g_qB + ((long)b * C_ + h * HD) * N_;
    const __nv_bfloat16* kBp = g_kB + ((long)b * C_ + h * HD) * N_;
    const __nv_bfloat16* vBp = g_vB + ((long)b * C_ + h * HD) * N_;

    __shared__ __align__(16) __nv_bfloat16 qsm[32 * QSTR];
    __shared__ __align__(16) __nv_bfloat16 ksm[2][32 * KSTR];
    __shared__ __align__(16) __nv_bfloat16 vsm[2][32 * KSTR];
    __shared__ float osm[32][130];

    int tid = threadIdx.x;
    int w = tid >> 5, lane = tid & 31;
    int g = lane >> 2, t = lane & 3;

    auto loadKV = [&](int m0, int s) {
        int row = tid >> 3, seg = tid & 7;
        cp16(&ksm[s][row * KSTR + seg * 8], kBp + (long)row * N_ + m0 + seg * 8);
        cp16(&vsm[s][row * KSTR + seg * 8], vBp + (long)row * N_ + m0 + seg * 8);
        cp_commit();
    };

    loadKV(0, 0);

    #pragma unroll
    for (int c = tid; c < 512; c += 256) {
        int row = c >> 4, seg = c & 15;
        reinterpret_cast<uint4*>(qsm + row * QSTR)[seg] =
            reinterpret_cast<const uint4*>(qBp + (long)row * N_ + n0)[seg];
    }
    __syncthreads();

    uint32_t aq[2][4];
    #pragma unroll
    for (int ku = 0; ku < 2; ku++) {
        int d = ku * 16 + ((lane >> 4) & 1) * 8 + (lane & 7);
        int col = w * 16 + ((lane >> 3) & 1) * 8;
        ldsm_x4t(aq[ku], qsm + d * QSTR + col);
    }

    float oacc[4][4];
    #pragma unroll
    for (int nd = 0; nd < 4; nd++)
        #pragma unroll
        for (int r = 0; r < 4; r++) oacc[nd][r] = 0.f;
    float lacc[4] = {0.f, 0.f, 0.f, 0.f};
    uint32_t bones[2];
    bones[0] = 0x3F803F80u; bones[1] = 0x3F803F80u;

    for (int it = 0; it < 16; it++) {
        int s = it & 1;
        if (it < 15) {
            loadKV((it + 1) * 64, s ^ 1);
            asm volatile("cp.async.wait_group 1;");
        } else {
            asm volatile("cp.async.wait_group 0;");
        }
        __syncthreads();

        float sS[8][4];
        #pragma unroll
        for (int ni = 0; ni < 8; ni++) {
            #pragma unroll
            for (int r = 0; r < 4; r++) sS[ni][r] = 0.f;
            #pragma unroll
            for (int ku = 0; ku < 2; ku++) {
                uint32_t bk[2];
                ldsm_x2t(bk, &ksm[s][(ku * 16 + (lane & 15)) * KSTR + ni * 8]);
                mma16816(sS[ni], aq[ku], bk);
            }
        }

        #pragma unroll
        for (int u = 0; u < 4; u++) {
            uint32_t ap[4];
            ap[0] = ex2_bf16x2(cvt2bf(sS[2*u][1],   sS[2*u][0]));
            ap[1] = ex2_bf16x2(cvt2bf(sS[2*u][3],   sS[2*u][2]));
            ap[2] = ex2_bf16x2(cvt2bf(sS[2*u+1][1], sS[2*u+1][0]));
            ap[3] = ex2_bf16x2(cvt2bf(sS[2*u+1][3], sS[2*u+1][2]));
            mma16816(lacc, ap, bones);
            #pragma unroll
            for (int nd = 0; nd < 4; nd++) {
                uint32_t bv[2];
                ldsm_x2(bv, &vsm[s][(nd * 8 + (lane & 7)) * KSTR + u * 16 + ((lane >> 3) & 1) * 8]);
                mma16816(oacc[nd], ap, bv);
            }
        }
        __syncthreads();
    }

    float inv0 = 1.f / lacc[0], inv1 = 1.f / lacc[2];

    #pragma unroll
    for (int nd = 0; nd < 4; nd++) {
        osm[nd * 8 + 2 * t][w * 16 + g]         = oacc[nd][0] * inv0;
        osm[nd * 8 + 2 * t + 1][w * 16 + g]     = oacc[nd][1] * inv0;
        osm[nd * 8 + 2 * t][w * 16 + g + 8]     = oacc[nd][2] * inv1;
        osm[nd * 8 + 2 * t + 1][w * 16 + g + 8] = oacc[nd][3] * inv1;
    }
    __syncthreads();

    const float* vfull = g_vf + ((long)b * C_ + h * HD) * N_ + n0;
    int n = tid & 127;
    float sqv = g_sq[b * N_ + n0 + n];
    #pragma unroll
    for (int d = tid >> 7; d < HD; d += 2) {
        float gated = sqv * osm[d][n] + (1.f - sqv) * vfull[(long)d * N_ + n];
        g_gh[((long)b * C_ + h * HD + d) * N_ + n0 + n] = __float2half_rn(gated);
    }
}

// ---------------- launch ----------------
extern "C" void kernel_launch(void* const* d_in, const int* in_sizes, int n_in,
                              void* d_out, int out_size) {
    const float* x   = (const float*)d_in[0];
    const float* gq  = (const float*)d_in[1];
    const float* gk  = (const float*)d_in[2];
    const float* Wsq = (const float*)d_in[3];
    const float* bsq = (const float*)d_in[4];
    const float* Wsk = (const float*)d_in[5];
    const float* bsk = (const float*)d_in[6];
    const float* Wq  = (const float*)d_in[7];
    const float* bq  = (const float*)d_in[8];
    const float* Wk  = (const float*)d_in[9];
    const float* bk  = (const float*)d_in[10];
    const float* Wv  = (const float*)d_in[11];
    const float* bv  = (const float*)d_in[12];
    const float* Wp  = (const float*)d_in[13];
    const float* bp  = (const float*)d_in[14];
    float* out = (float*)d_out;

    void *wh, *ball, *wph, *xh, *gh;
    cudaGetSymbolAddress(&wh,   g_wh);
    cudaGetSymbolAddress(&ball, g_ball);
    cudaGetSymbolAddress(&wph,  g_wph);
    cudaGetSymbolAddress(&xh,   g_xh);
    cudaGetSymbolAddress(&gh,   g_gh);

    assemble_kernel<<<MTOT + C_, 256>>>(Wq, bq, Wk, bk, Wv, bv, Wsq, bsq, Wsk, bsk, Wp);
    xcvt_kernel<<<(B_ * C_ * N_) / 1024, 256>>>(x);

    {   // gate GEMM + softmax (8 valid rows, no Y write)
        dim3 g(N_ / 128, 1, B_);
        gemmh_kernel<2><<<g, 256>>>((const __half*)wh + PR_ * C_, (const float*)ball + PR_,
                                    (const __half*)xh, nullptr,
                                    8, (long)C_ * N_, 0, gq, gk);
    }

    {   // gemm1: fused projection + gated q/k/v conversion (768 rows)
        dim3 g(N_ / 128, PR_ / 128, B_);
        gemmh_kernel<1><<<g, 256>>>((const __half*)wh, (const float*)ball,
                                    (const __half*)xh, nullptr,
                                    PR_, (long)C_ * N_, 0, nullptr, nullptr);
    }

    {   // attention + blend -> fp16 gated
        dim3 g(N_ / 128, NH, B_);
        attn_kernel<<<g, 256>>>();
    }

    {   // gemm2: out = Wp @ gated
        dim3 g(N_ / 128, C_ / 128, B_);
        gemmh_kernel<0><<<g, 256>>>((const __half*)wph, bp,
                                    (const __half*)gh, out,
                                    C_, (long)C_ * N_, (long)C_ * N_, nullptr, nullptr);
    }
}

// round 13
// speedup vs baseline: 1.0768x; 1.0768x over previous
#include <cuda_runtime.h>
#include <cuda_bf16.h>
#include <cuda_fp16.h>
#include <cstdint>

#define B_    8
#define C_    256
#define N_    1024
#define NH    8
#define HD    32
#define R_    4
#define MTOT  776
#define PR_   768
#define SCALE 0.17677669529663689f
#define LOG2E 1.4426950408889634f

// ---------------- scratch ----------------
__device__ float g_vf[B_ * C_ * N_];          // v projection fp32 (shortcut blend)
__device__ float g_sq[B_ * N_];
__device__ float g_sk[B_ * N_];
__device__ float g_ball[MTOT];
__device__ __half g_wh[MTOT * C_];            // stacked W (fp16): q,k,v,gq,gk rows
__device__ __half g_wph[C_ * C_];             // Wp (fp16)
__device__ __half g_xh[B_ * C_ * N_];         // x (fp16)
__device__ __nv_bfloat16 g_qB[B_ * C_ * N_];  // gated*SCALE*LOG2E
__device__ __nv_bfloat16 g_kB[B_ * C_ * N_];  // gated
__device__ __nv_bfloat16 g_vB[B_ * C_ * N_];
__device__ __half g_gh[B_ * C_ * N_];         // gated output (fp16, gemm2 input)

// ---------------- ptx helpers ----------------
__device__ __forceinline__ void cp16(void* d, const void* s) {
    uint32_t ds = (uint32_t)__cvta_generic_to_shared(d);
    asm volatile("cp.async.cg.shared.global [%0], [%1], 16;" :: "r"(ds), "l"(s));
}
__device__ __forceinline__ void cp_commit() { asm volatile("cp.async.commit_group;"); }

__device__ __forceinline__ void ldsm_x4(uint32_t (&r)[4], const void* p) {
    uint32_t a = (uint32_t)__cvta_generic_to_shared(p);
    asm volatile("ldmatrix.sync.aligned.m8n8.x4.shared.b16 {%0,%1,%2,%3},[%4];"
                 : "=r"(r[0]), "=r"(r[1]), "=r"(r[2]), "=r"(r[3]) : "r"(a));
}
__device__ __forceinline__ void ldsm_x4t(uint32_t (&r)[4], const void* p) {
    uint32_t a = (uint32_t)__cvta_generic_to_shared(p);
    asm volatile("ldmatrix.sync.aligned.m8n8.x4.trans.shared.b16 {%0,%1,%2,%3},[%4];"
                 : "=r"(r[0]), "=r"(r[1]), "=r"(r[2]), "=r"(r[3]) : "r"(a));
}
__device__ __forceinline__ void ldsm_x2(uint32_t (&r)[2], const void* p) {
    uint32_t a = (uint32_t)__cvta_generic_to_shared(p);
    asm volatile("ldmatrix.sync.aligned.m8n8.x2.shared.b16 {%0,%1},[%2];"
                 : "=r"(r[0]), "=r"(r[1]) : "r"(a));
}
__device__ __forceinline__ void ldsm_x2t(uint32_t (&r)[2], const void* p) {
    uint32_t a = (uint32_t)__cvta_generic_to_shared(p);
    asm volatile("ldmatrix.sync.aligned.m8n8.x2.trans.shared.b16 {%0,%1},[%2];"
                 : "=r"(r[0]), "=r"(r[1]) : "r"(a));
}
__device__ __forceinline__ void mma16816(float (&d)[4], const uint32_t (&a)[4], const uint32_t (&b)[2]) {
    asm volatile(
        "mma.sync.aligned.m16n8k16.row.col.f32.bf16.bf16.f32 "
        "{%0,%1,%2,%3},{%4,%5,%6,%7},{%8,%9},{%0,%1,%2,%3};"
        : "+f"(d[0]), "+f"(d[1]), "+f"(d[2]), "+f"(d[3])
        : "r"(a[0]), "r"(a[1]), "r"(a[2]), "r"(a[3]), "r"(b[0]), "r"(b[1]));
}
__device__ __forceinline__ void mmah16816(float (&d)[4], const uint32_t (&a)[4], const uint32_t (&b)[2]) {
    asm volatile(
        "mma.sync.aligned.m16n8k16.row.col.f32.f16.f16.f32 "
        "{%0,%1,%2,%3},{%4,%5,%6,%7},{%8,%9},{%0,%1,%2,%3};"
        : "+f"(d[0]), "+f"(d[1]), "+f"(d[2]), "+f"(d[3])
        : "r"(a[0]), "r"(a[1]), "r"(a[2]), "r"(a[3]), "r"(b[0]), "r"(b[1]));
}
__device__ __forceinline__ uint32_t packbf(float lo, float hi) {
    __nv_bfloat162 t = __floats2bfloat162_rn(lo, hi);
    return *reinterpret_cast<uint32_t*>(&t);
}
__device__ __forceinline__ uint32_t cvt2bf(float hi, float lo) {
    uint32_t y; asm("cvt.rn.bf16x2.f32 %0, %1, %2;" : "=r"(y) : "f"(hi), "f"(lo)); return y;
}
__device__ __forceinline__ uint32_t ex2_bf16x2(uint32_t x) {
    uint32_t y; asm("ex2.approx.ftz.bf16x2 %0, %1;" : "=r"(y) : "r"(x)); return y;
}

// ---------------- assemble weights -> fp16 ----------------
__global__ void assemble_kernel(
    const float* __restrict__ Wq, const float* __restrict__ bq,
    const float* __restrict__ Wk, const float* __restrict__ bk,
    const float* __restrict__ Wv, const float* __restrict__ bv,
    const float* __restrict__ Wsq, const float* __restrict__ bsq,
    const float* __restrict__ Wsk, const float* __restrict__ bsk,
    const float* __restrict__ Wp)
{
    int o = blockIdx.x;
    int k = threadIdx.x;
    if (o < MTOT) {
        const float* src; const float* bs; int r;
        if (o < 256)      { src = Wq  + o * 256;       bs = bq;  r = o; }
        else if (o < 512) { src = Wk  + (o-256) * 256; bs = bk;  r = o - 256; }
        else if (o < 768) { src = Wv  + (o-512) * 256; bs = bv;  r = o - 512; }
        else if (o < 772) { src = Wsq + (o-768) * 256; bs = bsq; r = o - 768; }
        else              { src = Wsk + (o-772) * 256; bs = bsk; r = o - 772; }
        g_wh[o * 256 + k] = __float2half_rn(src[k]);
        if (k == 0) g_ball[o] = bs[r];
    } else {
        int r = o - MTOT;
        g_wph[r * 256 + k] = __float2half_rn(Wp[r * 256 + k]);
    }
}

// ---------------- x -> fp16 (float4) ----------------
__global__ void xcvt_kernel(const float* __restrict__ x) {
    int i = (blockIdx.x * 256 + threadIdx.x) * 4;
    float4 v = *reinterpret_cast<const float4*>(x + i);
    __half2 p0 = __floats2half2_rn(v.x, v.y);
    __half2 p1 = __floats2half2_rn(v.z, v.w);
    uint2 o;
    o.x = *reinterpret_cast<uint32_t*>(&p0);
    o.y = *reinterpret_cast<uint32_t*>(&p1);
    *reinterpret_cast<uint2*>(g_xh + i) = o;
}

// ---------------- fp16 GEMM, BK=32, templated epilogue ----------------
// MODE 0: plain fp32 Y write (gemm2)
// MODE 1: fused qkv convert (gemm1)
// MODE 2: gate GEMM (8 valid rows) -> gumbel softmax
#define ASTR 40   // 80B row stride: (20r+4h) mod 32 -> conflict-free ldsm phases
template<int MODE>
__global__ __launch_bounds__(256) void gemmh_kernel(
    const __half* __restrict__ W, const float* __restrict__ bias,
    const __half* __restrict__ X, float* __restrict__ Y,
    int Ma, long xStride, long yStride,
    const float* __restrict__ gq, const float* __restrict__ gk)
{
    int b  = blockIdx.z;
    int m0 = blockIdx.y * 128;
    int n0 = blockIdx.x * 128;
    const __half* XB = X + (long)b * xStride;

    __shared__ __align__(16) __half sA[2][128 * ASTR];
    __shared__ __align__(16) __half sB[2][32 * 136];
    __shared__ float sg[8][132];

    int tid  = threadIdx.x;
    int warp = tid >> 5, lane = tid & 31;
    int wm = warp >> 2, wn = warp & 3;
    int g = lane >> 2, t = lane & 3;

    float acc[4][4][4];
    #pragma unroll
    for (int mi = 0; mi < 4; mi++)
        #pragma unroll
        for (int ni = 0; ni < 4; ni++)
            #pragma unroll
            for (int r = 0; r < 4; r++) acc[mi][ni][r] = 0.f;

    auto loadStage = [&](int step, int s) {
        int k0 = step * 32;
        #pragma unroll
        for (int c = 0; c < 2; c++) {   // A: 128 rows x 64B = 512 chunks
            int idx = tid + c * 256;
            int row = idx >> 2, quarter = idx & 3;
            int gm = m0 + row;
            __half* d = &sA[s][row * ASTR + quarter * 8];
            if (gm < Ma) cp16(d, W + gm * 256 + k0 + quarter * 8);
            else         *reinterpret_cast<uint4*>(d) = make_uint4(0,0,0,0);
        }
        #pragma unroll
        for (int c = 0; c < 2; c++) {   // B: 32 rows x 256B = 512 chunks
            int idx = tid + c * 256;
            int row = idx >> 4, seg = idx & 15;
            cp16(&sB[s][row * 136 + seg * 8], XB + (long)(k0 + row) * N_ + n0 + seg * 8);
        }
        cp_commit();
    };

    loadStage(0, 0);
    for (int step = 0; step < 8; step++) {
        int s = step & 1;
        if (step < 7) {
            loadStage(step + 1, s ^ 1);
            asm volatile("cp.async.wait_group 1;");
        } else {
            asm volatile("cp.async.wait_group 0;");
        }
        __syncthreads();

        uint32_t afr[2][4][4];
        #pragma unroll
        for (int ku = 0; ku < 2; ku++)
            #pragma unroll
            for (int mi = 0; mi < 4; mi++) {
                const __half* p = &sA[s][(wm * 64 + mi * 16 + (lane & 15)) * ASTR + ku * 16] + ((lane >> 4) & 1) * 8;
                ldsm_x4(afr[ku][mi], p);
            }
        uint32_t bfr[2][4][2];
        #pragma unroll
        for (int ku = 0; ku < 2; ku++)
            #pragma unroll
            for (int ni = 0; ni < 4; ni++) {
                const __half* p = &sB[s][(ku * 16 + (lane & 15)) * 136 + wn * 32 + ni * 8];
                ldsm_x2t(bfr[ku][ni], p);
            }
        #pragma unroll
        for (int mi = 0; mi < 4; mi++)
            #pragma unroll
            for (int ni = 0; ni < 4; ni++) {
                mmah16816(acc[mi][ni], afr[0][mi], bfr[0][ni]);
                mmah16816(acc[mi][ni], afr[1][mi], bfr[1][ni]);
            }
        __syncthreads();
    }

    if (MODE == 0) {
        float* Yb = Y + (long)b * yStride;
        #pragma unroll
        for (int mi = 0; mi < 4; mi++) {
            int r0 = m0 + wm * 64 + mi * 16 + g;
            int r1 = r0 + 8;
            float bv0 = bias[r0], bv1 = bias[r1];
            #pragma unroll
            for (int ni = 0; ni < 4; ni++) {
                int col = n0 + wn * 32 + ni * 8 + 2 * t;
                Yb[(long)r0 * N_ + col]     = acc[mi][ni][0] + bv0;
                Yb[(long)r0 * N_ + col + 1] = acc[mi][ni][1] + bv0;
                Yb[(long)r1 * N_ + col]     = acc[mi][ni][2] + bv1;
                Yb[(long)r1 * N_ + col + 1] = acc[mi][ni][3] + bv1;
            }
        }
    } else if (MODE == 1) {
        const float QMUL = SCALE * LOG2E;
        int cat = m0 >> 8;
        const float* sqb = g_sq + (long)b * N_;
        const float* skb = g_sk + (long)b * N_;
        #pragma unroll
        for (int mi = 0; mi < 4; mi++) {
            int gr0 = m0 + wm * 64 + mi * 16 + g;
            int rr0 = gr0 & 255, rr1 = rr0 + 8;
            float bv0 = bias[gr0], bv1 = bias[gr0 + 8];
            long o0 = ((long)b * C_ + rr0) * N_;
            long o1 = ((long)b * C_ + rr1) * N_;
            #pragma unroll
            for (int ni = 0; ni < 4; ni++) {
                int col = n0 + wn * 32 + ni * 8 + 2 * t;
                float a0 = acc[mi][ni][0] + bv0, a1 = acc[mi][ni][1] + bv0;
                float a2 = acc[mi][ni][2] + bv1, a3 = acc[mi][ni][3] + bv1;
                if (cat == 0) {
                    float2 s = *reinterpret_cast<const float2*>(sqb + col);
                    *reinterpret_cast<uint32_t*>(g_qB + o0 + col) = packbf(a0 * s.x * QMUL, a1 * s.y * QMUL);
                    *reinterpret_cast<uint32_t*>(g_qB + o1 + col) = packbf(a2 * s.x * QMUL, a3 * s.y * QMUL);
                } else if (cat == 1) {
                    float2 s = *reinterpret_cast<const float2*>(skb + col);
                    *reinterpret_cast<uint32_t*>(g_kB + o0 + col) = packbf(a0 * s.x, a1 * s.y);
                    *reinterpret_cast<uint32_t*>(g_kB + o1 + col) = packbf(a2 * s.x, a3 * s.y);
                } else {
                    *reinterpret_cast<uint32_t*>(g_vB + o0 + col) = packbf(a0, a1);
                    *reinterpret_cast<uint32_t*>(g_vB + o1 + col) = packbf(a2, a3);
                    *reinterpret_cast<float2*>(g_vf + o0 + col) = make_float2(a0, a1);
                    *reinterpret_cast<float2*>(g_vf + o1 + col) = make_float2(a2, a3);
                }
            }
        }
    } else {
        if (wm == 0) {
            float bv = bias[g];
            #pragma unroll
            for (int ni = 0; ni < 4; ni++) {
                int col = wn * 32 + ni * 8 + 2 * t;
                sg[g][col]     = acc[0][ni][0] + bv;
                sg[g][col + 1] = acc[0][ni][1] + bv;
            }
        }
        __syncthreads();
        if (tid < 128) {
            int n = n0 + tid;
            float lq[4], lk[4];
            #pragma unroll
            for (int r = 0; r < 4; r++) {
                lq[r] = sg[r][tid]     + gq[(b * R_ + r) * N_ + n];
                lk[r] = sg[4 + r][tid] + gk[(b * R_ + r) * N_ + n];
            }
            float mq = fmaxf(fmaxf(lq[0], lq[1]), fmaxf(lq[2], lq[3]));
            float s2 = 0.f;
            #pragma unroll
            for (int r = 0; r < 4; r++) s2 += __expf(lq[r] - mq);
            g_sq[b * N_ + n] = __expf(lq[0] - mq) / s2;
            float mk = fmaxf(fmaxf(lk[0], lk[1]), fmaxf(lk[2], lk[3]));
            s2 = 0.f;
            #pragma unroll
            for (int r = 0; r < 4; r++) s2 += __expf(lk[r] - mk);
            g_sk[b * N_ + n] = __expf(lk[0] - mk) / s2;
        }
    }
}

// ---------------- flash attention: bf16x2 exp + ones-MMA row sums ----------------
#define QSTR 136
#define KSTR 72
__global__ __launch_bounds__(256) void attn_kernel() {
    int b = blockIdx.z, h = blockIdx.y;
    int n0 = blockIdx.x * 128;
    const __nv_bfloat16* qBp = g_qB + ((long)b * C_ + h * HD) * N_;
    const __nv_bfloat16* kBp = g_kB + ((long)b * C_ + h * HD) * N_;
    const __nv_bfloat16* vBp = g_vB + ((long)b * C_ + h * HD) * N_;

    __shared__ __align__(16) __nv_bfloat16 qsm[32 * QSTR];
    __shared__ __align__(16) __nv_bfloat16 ksm[2][32 * KSTR];
    __shared__ __align__(16) __nv_bfloat16 vsm[2][32 * KSTR];
    __shared__ float osm[32][130];

    int tid = threadIdx.x;
    int w = tid >> 5, lane = tid & 31;
    int g = lane >> 2, t = lane & 3;

    auto loadKV = [&](int m0, int s) {
        int row = tid >> 3, seg = tid & 7;
        cp16(&ksm[s][row * KSTR + seg * 8], kBp + (long)row * N_ + m0 + seg * 8);
        cp16(&vsm[s][row * KSTR + seg * 8], vBp + (long)row * N_ + m0 + seg * 8);
        cp_commit();
    };

    loadKV(0, 0);

    #pragma unroll
    for (int c = tid; c < 512; c += 256) {
        int row = c >> 4, seg = c & 15;
        reinterpret_cast<uint4*>(qsm + row * QSTR)[seg] =
            reinterpret_cast<const uint4*>(qBp + (long)row * N_ + n0)[seg];
    }
    __syncthreads();

    uint32_t aq[2][4];
    #pragma unroll
    for (int ku = 0; ku < 2; ku++) {
        int d = ku * 16 + ((lane >> 4) & 1) * 8 + (lane & 7);
        int col = w * 16 + ((lane >> 3) & 1) * 8;
        ldsm_x4t(aq[ku], qsm + d * QSTR + col);
    }

    float oacc[4][4];
    #pragma unroll
    for (int nd = 0; nd < 4; nd++)
        #pragma unroll
        for (int r = 0; r < 4; r++) oacc[nd][r] = 0.f;
    float lacc[4] = {0.f, 0.f, 0.f, 0.f};
    uint32_t bones[2];
    bones[0] = 0x3F803F80u; bones[1] = 0x3F803F80u;

    for (int it = 0; it < 16; it++) {
        int s = it & 1;
        if (it < 15) {
            loadKV((it + 1) * 64, s ^ 1);
            asm volatile("cp.async.wait_group 1;");
        } else {
            asm volatile("cp.async.wait_group 0;");
        }
        __syncthreads();

        float sS[8][4];
        #pragma unroll
        for (int ni = 0; ni < 8; ni++) {
            #pragma unroll
            for (int r = 0; r < 4; r++) sS[ni][r] = 0.f;
            #pragma unroll
            for (int ku = 0; ku < 2; ku++) {
                uint32_t bk[2];
                ldsm_x2t(bk, &ksm[s][(ku * 16 + (lane & 15)) * KSTR + ni * 8]);
                mma16816(sS[ni], aq[ku], bk);
            }
        }

        #pragma unroll
        for (int u = 0; u < 4; u++) {
            uint32_t ap[4];
            ap[0] = ex2_bf16x2(cvt2bf(sS[2*u][1],   sS[2*u][0]));
            ap[1] = ex2_bf16x2(cvt2bf(sS[2*u][3],   sS[2*u][2]));
            ap[2] = ex2_bf16x2(cvt2bf(sS[2*u+1][1], sS[2*u+1][0]));
            ap[3] = ex2_bf16x2(cvt2bf(sS[2*u+1][3], sS[2*u+1][2]));
            mma16816(lacc, ap, bones);
            #pragma unroll
            for (int nd = 0; nd < 4; nd++) {
                uint32_t bv[2];
                ldsm_x2(bv, &vsm[s][(nd * 8 + (lane & 7)) * KSTR + u * 16 + ((lane >> 3) & 1) * 8]);
                mma16816(oacc[nd], ap, bv);
            }
        }
        __syncthreads();
    }

    float inv0 = 1.f / lacc[0], inv1 = 1.f / lacc[2];

    #pragma unroll
    for (int nd = 0; nd < 4; nd++) {
        osm[nd * 8 + 2 * t][w * 16 + g]         = oacc[nd][0] * inv0;
        osm[nd * 8 + 2 * t + 1][w * 16 + g]     = oacc[nd][1] * inv0;
        osm[nd * 8 + 2 * t][w * 16 + g + 8]     = oacc[nd][2] * inv1;
        osm[nd * 8 + 2 * t + 1][w * 16 + g + 8] = oacc[nd][3] * inv1;
    }
    __syncthreads();

    const float* vfull = g_vf + ((long)b * C_ + h * HD) * N_ + n0;
    int n = tid & 127;
    float sqv = g_sq[b * N_ + n0 + n];
    #pragma unroll
    for (int d = tid >> 7; d < HD; d += 2) {
        float gated = sqv * osm[d][n] + (1.f - sqv) * vfull[(long)d * N_ + n];
        g_gh[((long)b * C_ + h * HD + d) * N_ + n0 + n] = __float2half_rn(gated);
    }
}

// ---------------- launch ----------------
extern "C" void kernel_launch(void* const* d_in, const int* in_sizes, int n_in,
                              void* d_out, int out_size) {
    const float* x   = (const float*)d_in[0];
    const float* gq  = (const float*)d_in[1];
    const float* gk  = (const float*)d_in[2];
    const float* Wsq = (const float*)d_in[3];
    const float* bsq = (const float*)d_in[4];
    const float* Wsk = (const float*)d_in[5];
    const float* bsk = (const float*)d_in[6];
    const float* Wq  = (const float*)d_in[7];
    const float* bq  = (const float*)d_in[8];
    const float* Wk  = (const float*)d_in[9];
    const float* bk  = (const float*)d_in[10];
    const float* Wv  = (const float*)d_in[11];
    const float* bv  = (const float*)d_in[12];
    const float* Wp  = (const float*)d_in[13];
    const float* bp  = (const float*)d_in[14];
    float* out = (float*)d_out;

    void *wh, *ball, *wph, *xh, *gh;
    cudaGetSymbolAddress(&wh,   g_wh);
    cudaGetSymbolAddress(&ball, g_ball);
    cudaGetSymbolAddress(&wph,  g_wph);
    cudaGetSymbolAddress(&xh,   g_xh);
    cudaGetSymbolAddress(&gh,   g_gh);

    assemble_kernel<<<MTOT + C_, 256>>>(Wq, bq, Wk, bk, Wv, bv, Wsq, bsq, Wsk, bsk, Wp);
    xcvt_kernel<<<(B_ * C_ * N_) / 1024, 256>>>(x);

    {   // gate GEMM + softmax (8 valid rows, no Y write)
        dim3 g(N_ / 128, 1, B_);
        gemmh_kernel<2><<<g, 256>>>((const __half*)wh + PR_ * C_, (const float*)ball + PR_,
                                    (const __half*)xh, nullptr,
                                    8, (long)C_ * N_, 0, gq, gk);
    }

    {   // gemm1: fused projection + gated q/k/v conversion (768 rows)
        dim3 g(N_ / 128, PR_ / 128, B_);
        gemmh_kernel<1><<<g, 256>>>((const __half*)wh, (const float*)ball,
                                    (const __half*)xh, nullptr,
                                    PR_, (long)C_ * N_, 0, nullptr, nullptr);
    }

    {   // attention + blend -> fp16 gated
        dim3 g(N_ / 128, NH, B_);
        attn_kernel<<<g, 256>>>();
    }

    {   // gemm2: out = Wp @ gated
        dim3 g(N_ / 128, C_ / 128, B_);
        gemmh_kernel<0><<<g, 256>>>((const __half*)wph, bp,
                                    (const __half*)gh, out,
                                    C_, (long)C_ * N_, (long)C_ * N_, nullptr, nullptr);
    }
}

// round 14
// speedup vs baseline: 1.1065x; 1.0276x over previous
#include <cuda_runtime.h>
#include <cuda_bf16.h>
#include <cuda_fp16.h>
#include <cstdint>

#define B_    8
#define C_    256
#define N_    1024
#define NH    8
#define HD    32
#define R_    4
#define MTOT  776
#define PR_   768
#define SCALE 0.17677669529663689f
#define LOG2E 1.4426950408889634f

// ---------------- scratch ----------------
__device__ float g_vf[B_ * C_ * N_];          // v projection fp32 (shortcut blend)
__device__ float g_sq[B_ * N_];
__device__ float g_sk[B_ * N_];
__device__ float g_ball[MTOT];
__device__ __half g_wh[MTOT * C_];            // stacked W (fp16): q,k,v,gq,gk rows
__device__ __half g_wph[C_ * C_];             // Wp (fp16)
__device__ __half g_xh[B_ * C_ * N_];         // x (fp16)
__device__ __nv_bfloat16 g_qB[B_ * C_ * N_];  // UNGATED q (bf16)
__device__ __nv_bfloat16 g_kB[B_ * C_ * N_];  // UNGATED k (bf16)
__device__ __nv_bfloat16 g_vB[B_ * C_ * N_];
__device__ __half g_gh[B_ * C_ * N_];         // gated output (fp16, gemm2 input)

// ---------------- ptx helpers ----------------
__device__ __forceinline__ void cp16(void* d, const void* s) {
    uint32_t ds = (uint32_t)__cvta_generic_to_shared(d);
    asm volatile("cp.async.cg.shared.global [%0], [%1], 16;" :: "r"(ds), "l"(s));
}
__device__ __forceinline__ void cp_commit() { asm volatile("cp.async.commit_group;"); }

__device__ __forceinline__ void ldsm_x4(uint32_t (&r)[4], const void* p) {
    uint32_t a = (uint32_t)__cvta_generic_to_shared(p);
    asm volatile("ldmatrix.sync.aligned.m8n8.x4.shared.b16 {%0,%1,%2,%3},[%4];"
                 : "=r"(r[0]), "=r"(r[1]), "=r"(r[2]), "=r"(r[3]) : "r"(a));
}
__device__ __forceinline__ void ldsm_x4t(uint32_t (&r)[4], const void* p) {
    uint32_t a = (uint32_t)__cvta_generic_to_shared(p);
    asm volatile("ldmatrix.sync.aligned.m8n8.x4.trans.shared.b16 {%0,%1,%2,%3},[%4];"
                 : "=r"(r[0]), "=r"(r[1]), "=r"(r[2]), "=r"(r[3]) : "r"(a));
}
__device__ __forceinline__ void ldsm_x2(uint32_t (&r)[2], const void* p) {
    uint32_t a = (uint32_t)__cvta_generic_to_shared(p);
    asm volatile("ldmatrix.sync.aligned.m8n8.x2.shared.b16 {%0,%1},[%2];"
                 : "=r"(r[0]), "=r"(r[1]) : "r"(a));
}
__device__ __forceinline__ void ldsm_x2t(uint32_t (&r)[2], const void* p) {
    uint32_t a = (uint32_t)__cvta_generic_to_shared(p);
    asm volatile("ldmatrix.sync.aligned.m8n8.x2.trans.shared.b16 {%0,%1},[%2];"
                 : "=r"(r[0]), "=r"(r[1]) : "r"(a));
}
__device__ __forceinline__ void mma16816(float (&d)[4], const uint32_t (&a)[4], const uint32_t (&b)[2]) {
    asm volatile(
        "mma.sync.aligned.m16n8k16.row.col.f32.bf16.bf16.f32 "
        "{%0,%1,%2,%3},{%4,%5,%6,%7},{%8,%9},{%0,%1,%2,%3};"
        : "+f"(d[0]), "+f"(d[1]), "+f"(d[2]), "+f"(d[3])
        : "r"(a[0]), "r"(a[1]), "r"(a[2]), "r"(a[3]), "r"(b[0]), "r"(b[1]));
}
__device__ __forceinline__ void mmah16816(float (&d)[4], const uint32_t (&a)[4], const uint32_t (&b)[2]) {
    asm volatile(
        "mma.sync.aligned.m16n8k16.row.col.f32.f16.f16.f32 "
        "{%0,%1,%2,%3},{%4,%5,%6,%7},{%8,%9},{%0,%1,%2,%3};"
        : "+f"(d[0]), "+f"(d[1]), "+f"(d[2]), "+f"(d[3])
        : "r"(a[0]), "r"(a[1]), "r"(a[2]), "r"(a[3]), "r"(b[0]), "r"(b[1]));
}
__device__ __forceinline__ uint32_t packbf(float lo, float hi) {
    __nv_bfloat162 t = __floats2bfloat162_rn(lo, hi);
    return *reinterpret_cast<uint32_t*>(&t);
}
__device__ __forceinline__ uint32_t cvt2bf(float hi, float lo) {
    uint32_t y; asm("cvt.rn.bf16x2.f32 %0, %1, %2;" : "=r"(y) : "f"(hi), "f"(lo)); return y;
}
__device__ __forceinline__ uint32_t ex2_bf16x2(uint32_t x) {
    uint32_t y; asm("ex2.approx.ftz.bf16x2 %0, %1;" : "=r"(y) : "r"(x)); return y;
}

// ---------------- assemble weights -> fp16 ----------------
__global__ void assemble_kernel(
    const float* __restrict__ Wq, const float* __restrict__ bq,
    const float* __restrict__ Wk, const float* __restrict__ bk,
    const float* __restrict__ Wv, const float* __restrict__ bv,
    const float* __restrict__ Wsq, const float* __restrict__ bsq,
    const float* __restrict__ Wsk, const float* __restrict__ bsk,
    const float* __restrict__ Wp)
{
    int o = blockIdx.x;
    int k = threadIdx.x;
    if (o < MTOT) {
        const float* src; const float* bs; int r;
        if (o < 256)      { src = Wq  + o * 256;       bs = bq;  r = o; }
        else if (o < 512) { src = Wk  + (o-256) * 256; bs = bk;  r = o - 256; }
        else if (o < 768) { src = Wv  + (o-512) * 256; bs = bv;  r = o - 512; }
        else if (o < 772) { src = Wsq + (o-768) * 256; bs = bsq; r = o - 768; }
        else              { src = Wsk + (o-772) * 256; bs = bsk; r = o - 772; }
        g_wh[o * 256 + k] = __float2half_rn(src[k]);
        if (k == 0) g_ball[o] = bs[r];
    } else {
        int r = o - MTOT;
        g_wph[r * 256 + k] = __float2half_rn(Wp[r * 256 + k]);
    }
}

// ---------------- x -> fp16 (float4) ----------------
__global__ void xcvt_kernel(const float* __restrict__ x) {
    int i = (blockIdx.x * 256 + threadIdx.x) * 4;
    float4 v = *reinterpret_cast<const float4*>(x + i);
    __half2 p0 = __floats2half2_rn(v.x, v.y);
    __half2 p1 = __floats2half2_rn(v.z, v.w);
    uint2 o;
    o.x = *reinterpret_cast<uint32_t*>(&p0);
    o.y = *reinterpret_cast<uint32_t*>(&p1);
    *reinterpret_cast<uint2*>(g_xh + i) = o;
}

// ---------------- fp16 GEMM, BK=32, templated epilogue ----------------
// MODE 0: plain fp32 Y write (gemm2)
// MODE 1: gemm1 — q/k/v ungated bf16 write; m0==768 tile does gate softmax
#define ASTR 40
template<int MODE>
__global__ __launch_bounds__(256) void gemmh_kernel(
    const __half* __restrict__ W, const float* __restrict__ bias,
    const __half* __restrict__ X, float* __restrict__ Y,
    int Ma, long xStride, long yStride,
    const float* __restrict__ gq, const float* __restrict__ gk)
{
    int b  = blockIdx.z;
    int m0 = blockIdx.y * 128;
    int n0 = blockIdx.x * 128;
    const __half* XB = X + (long)b * xStride;

    __shared__ __align__(16) __half sA[2][128 * ASTR];
    __shared__ __align__(16) __half sB[2][32 * 136];
    __shared__ float sg[8][132];

    int tid  = threadIdx.x;
    int warp = tid >> 5, lane = tid & 31;
    int wm = warp >> 2, wn = warp & 3;
    int g = lane >> 2, t = lane & 3;

    float acc[4][4][4];
    #pragma unroll
    for (int mi = 0; mi < 4; mi++)
        #pragma unroll
        for (int ni = 0; ni < 4; ni++)
            #pragma unroll
            for (int r = 0; r < 4; r++) acc[mi][ni][r] = 0.f;

    auto loadStage = [&](int step, int s) {
        int k0 = step * 32;
        #pragma unroll
        for (int c = 0; c < 2; c++) {
            int idx = tid + c * 256;
            int row = idx >> 2, quarter = idx & 3;
            int gm = m0 + row;
            __half* d = &sA[s][row * ASTR + quarter * 8];
            if (gm < Ma) cp16(d, W + gm * 256 + k0 + quarter * 8);
            else         *reinterpret_cast<uint4*>(d) = make_uint4(0,0,0,0);
        }
        #pragma unroll
        for (int c = 0; c < 2; c++) {
            int idx = tid + c * 256;
            int row = idx >> 4, seg = idx & 15;
            cp16(&sB[s][row * 136 + seg * 8], XB + (long)(k0 + row) * N_ + n0 + seg * 8);
        }
        cp_commit();
    };

    loadStage(0, 0);
    for (int step = 0; step < 8; step++) {
        int s = step & 1;
        if (step < 7) {
            loadStage(step + 1, s ^ 1);
            asm volatile("cp.async.wait_group 1;");
        } else {
            asm volatile("cp.async.wait_group 0;");
        }
        __syncthreads();

        uint32_t afr[2][4][4];
        #pragma unroll
        for (int ku = 0; ku < 2; ku++)
            #pragma unroll
            for (int mi = 0; mi < 4; mi++) {
                const __half* p = &sA[s][(wm * 64 + mi * 16 + (lane & 15)) * ASTR + ku * 16] + ((lane >> 4) & 1) * 8;
                ldsm_x4(afr[ku][mi], p);
            }
        uint32_t bfr[2][4][2];
        #pragma unroll
        for (int ku = 0; ku < 2; ku++)
            #pragma unroll
            for (int ni = 0; ni < 4; ni++) {
                const __half* p = &sB[s][(ku * 16 + (lane & 15)) * 136 + wn * 32 + ni * 8];
                ldsm_x2t(bfr[ku][ni], p);
            }
        #pragma unroll
        for (int mi = 0; mi < 4; mi++)
            #pragma unroll
            for (int ni = 0; ni < 4; ni++) {
                mmah16816(acc[mi][ni], afr[0][mi], bfr[0][ni]);
                mmah16816(acc[mi][ni], afr[1][mi], bfr[1][ni]);
            }
        __syncthreads();
    }

    if (MODE == 0) {
        float* Yb = Y + (long)b * yStride;
        #pragma unroll
        for (int mi = 0; mi < 4; mi++) {
            int r0 = m0 + wm * 64 + mi * 16 + g;
            int r1 = r0 + 8;
            float bv0 = bias[r0], bv1 = bias[r1];
            #pragma unroll
            for (int ni = 0; ni < 4; ni++) {
                int col = n0 + wn * 32 + ni * 8 + 2 * t;
                Yb[(long)r0 * N_ + col]     = acc[mi][ni][0] + bv0;
                Yb[(long)r0 * N_ + col + 1] = acc[mi][ni][1] + bv0;
                Yb[(long)r1 * N_ + col]     = acc[mi][ni][2] + bv1;
                Yb[(long)r1 * N_ + col + 1] = acc[mi][ni][3] + bv1;
            }
        }
    } else {
        if (m0 < PR_) {
            // ungated q/k/v bf16 write (category uniform per block)
            int cat = m0 >> 8;
            __nv_bfloat16* dst = (cat == 0) ? g_qB : (cat == 1) ? g_kB : g_vB;
            #pragma unroll
            for (int mi = 0; mi < 4; mi++) {
                int gr0 = m0 + wm * 64 + mi * 16 + g;
                int rr0 = gr0 & 255, rr1 = rr0 + 8;
                float bv0 = bias[gr0], bv1 = bias[gr0 + 8];
                long o0 = ((long)b * C_ + rr0) * N_;
                long o1 = ((long)b * C_ + rr1) * N_;
                #pragma unroll
                for (int ni = 0; ni < 4; ni++) {
                    int col = n0 + wn * 32 + ni * 8 + 2 * t;
                    float a0 = acc[mi][ni][0] + bv0, a1 = acc[mi][ni][1] + bv0;
                    float a2 = acc[mi][ni][2] + bv1, a3 = acc[mi][ni][3] + bv1;
                    *reinterpret_cast<uint32_t*>(dst + o0 + col) = packbf(a0, a1);
                    *reinterpret_cast<uint32_t*>(dst + o1 + col) = packbf(a2, a3);
                    if (cat == 2) {
                        *reinterpret_cast<float2*>(g_vf + o0 + col) = make_float2(a0, a1);
                        *reinterpret_cast<float2*>(g_vf + o1 + col) = make_float2(a2, a3);
                    }
                }
            }
        } else {
            // gate softmax tile (rows 768-775 in wm==0, mi==0)
            if (wm == 0) {
                float bv = bias[768 + g];
                #pragma unroll
                for (int ni = 0; ni < 4; ni++) {
                    int col = wn * 32 + ni * 8 + 2 * t;
                    sg[g][col]     = acc[0][ni][0] + bv;
                    sg[g][col + 1] = acc[0][ni][1] + bv;
                }
            }
            __syncthreads();
            if (tid < 128) {
                int n = n0 + tid;
                float lq[4], lk[4];
                #pragma unroll
                for (int r = 0; r < 4; r++) {
                    lq[r] = sg[r][tid]     + gq[(b * R_ + r) * N_ + n];
                    lk[r] = sg[4 + r][tid] + gk[(b * R_ + r) * N_ + n];
                }
                float mq = fmaxf(fmaxf(lq[0], lq[1]), fmaxf(lq[2], lq[3]));
                float s2 = 0.f;
                #pragma unroll
                for (int r = 0; r < 4; r++) s2 += __expf(lq[r] - mq);
                g_sq[b * N_ + n] = __expf(lq[0] - mq) / s2;
                float mk = fmaxf(fmaxf(lk[0], lk[1]), fmaxf(lk[2], lk[3]));
                s2 = 0.f;
                #pragma unroll
                for (int r = 0; r < 4; r++) s2 += __expf(lk[r] - mk);
                g_sk[b * N_ + n] = __expf(lk[0] - mk) / s2;
            }
        }
    }
}

// ---------------- flash attention: gates folded into softmax ----------------
#define QSTR 136
#define KSTR 72
__global__ __launch_bounds__(256) void attn_kernel() {
    int b = blockIdx.z, h = blockIdx.y;
    int n0 = blockIdx.x * 128;
    const __nv_bfloat16* qBp = g_qB + ((long)b * C_ + h * HD) * N_;
    const __nv_bfloat16* kBp = g_kB + ((long)b * C_ + h * HD) * N_;
    const __nv_bfloat16* vBp = g_vB + ((long)b * C_ + h * HD) * N_;

    __shared__ __align__(16) __nv_bfloat16 qsm[32 * QSTR];
    __shared__ __align__(16) __nv_bfloat16 ksm[2][32 * KSTR];
    __shared__ __align__(16) __nv_bfloat16 vsm[2][32 * KSTR];
    __shared__ float ssk[N_];          // per-key gate values
    __shared__ float osm[32][130];

    int tid = threadIdx.x;
    int w = tid >> 5, lane = tid & 31;
    int g = lane >> 2, t = lane & 3;

    auto loadKV = [&](int m0, int s) {
        int row = tid >> 3, seg = tid & 7;
        cp16(&ksm[s][row * KSTR + seg * 8], kBp + (long)row * N_ + m0 + seg * 8);
        cp16(&vsm[s][row * KSTR + seg * 8], vBp + (long)row * N_ + m0 + seg * 8);
        cp_commit();
    };

    loadKV(0, 0);

    // preload sk (1024 floats) + Q tile
    *reinterpret_cast<float4*>(ssk + tid * 4) =
        *reinterpret_cast<const float4*>(g_sk + (long)b * N_ + tid * 4);
    #pragma unroll
    for (int c = tid; c < 512; c += 256) {
        int row = c >> 4, seg = c & 15;
        reinterpret_cast<uint4*>(qsm + row * QSTR)[seg] =
            reinterpret_cast<const uint4*>(qBp + (long)row * N_ + n0)[seg];
    }
    __syncthreads();

    uint32_t aq[2][4];
    #pragma unroll
    for (int ku = 0; ku < 2; ku++) {
        int d = ku * 16 + ((lane >> 4) & 1) * 8 + (lane & 7);
        int col = w * 16 + ((lane >> 3) & 1) * 8;
        ldsm_x4t(aq[ku], qsm + d * QSTR + col);
    }

    const float QMUL = SCALE * LOG2E;
    float c0 = QMUL * g_sq[(long)b * N_ + n0 + w * 16 + g];
    float c1 = QMUL * g_sq[(long)b * N_ + n0 + w * 16 + g + 8];

    float oacc[4][4];
    #pragma unroll
    for (int nd = 0; nd < 4; nd++)
        #pragma unroll
        for (int r = 0; r < 4; r++) oacc[nd][r] = 0.f;
    float lacc[4] = {0.f, 0.f, 0.f, 0.f};
    uint32_t bones[2];
    bones[0] = 0x3F803F80u; bones[1] = 0x3F803F80u;

    for (int it = 0; it < 16; it++) {
        int s = it & 1;
        if (it < 15) {
            loadKV((it + 1) * 64, s ^ 1);
            asm volatile("cp.async.wait_group 1;");
        } else {
            asm volatile("cp.async.wait_group 0;");
        }
        __syncthreads();

        float sS[8][4];
        #pragma unroll
        for (int ni = 0; ni < 8; ni++) {
            #pragma unroll
            for (int r = 0; r < 4; r++) sS[ni][r] = 0.f;
            #pragma unroll
            for (int ku = 0; ku < 2; ku++) {
                uint32_t bk[2];
                ldsm_x2t(bk, &ksm[s][(ku * 16 + (lane & 15)) * KSTR + ni * 8]);
                mma16816(sS[ni], aq[ku], bk);
            }
        }

        // gate scaling: S *= c_row * sk_col, then P = 2^S
        int km = it * 64;
        #pragma unroll
        for (int ni = 0; ni < 8; ni++) {
            float2 skp = *reinterpret_cast<const float2*>(ssk + km + ni * 8 + 2 * t);
            sS[ni][0] *= c0 * skp.x;
            sS[ni][1] *= c0 * skp.y;
            sS[ni][2] *= c1 * skp.x;
            sS[ni][3] *= c1 * skp.y;
        }

        #pragma unroll
        for (int u = 0; u < 4; u++) {
            uint32_t ap[4];
            ap[0] = ex2_bf16x2(cvt2bf(sS[2*u][1],   sS[2*u][0]));
            ap[1] = ex2_bf16x2(cvt2bf(sS[2*u][3],   sS[2*u][2]));
            ap[2] = ex2_bf16x2(cvt2bf(sS[2*u+1][1], sS[2*u+1][0]));
            ap[3] = ex2_bf16x2(cvt2bf(sS[2*u+1][3], sS[2*u+1][2]));
            mma16816(lacc, ap, bones);
            #pragma unroll
            for (int nd = 0; nd < 4; nd++) {
                uint32_t bv[2];
                ldsm_x2(bv, &vsm[s][(nd * 8 + (lane & 7)) * KSTR + u * 16 + ((lane >> 3) & 1) * 8]);
                mma16816(oacc[nd], ap, bv);
            }
        }
        __syncthreads();
    }

    float inv0 = 1.f / lacc[0], inv1 = 1.f / lacc[2];

    #pragma unroll
    for (int nd = 0; nd < 4; nd++) {
        osm[nd * 8 + 2 * t][w * 16 + g]         = oacc[nd][0] * inv0;
        osm[nd * 8 + 2 * t + 1][w * 16 + g]     = oacc[nd][1] * inv0;
        osm[nd * 8 + 2 * t][w * 16 + g + 8]     = oacc[nd][2] * inv1;
        osm[nd * 8 + 2 * t + 1][w * 16 + g + 8] = oacc[nd][3] * inv1;
    }
    __syncthreads();

    const float* vfull = g_vf + ((long)b * C_ + h * HD) * N_ + n0;
    int n = tid & 127;
    float sqv = g_sq[(long)b * N_ + n0 + n];
    #pragma unroll
    for (int d = tid >> 7; d < HD; d += 2) {
        float gated = sqv * osm[d][n] + (1.f - sqv) * vfull[(long)d * N_ + n];
        g_gh[((long)b * C_ + h * HD + d) * N_ + n0 + n] = __float2half_rn(gated);
    }
}

// ---------------- launch ----------------
extern "C" void kernel_launch(void* const* d_in, const int* in_sizes, int n_in,
                              void* d_out, int out_size) {
    const float* x   = (const float*)d_in[0];
    const float* gq  = (const float*)d_in[1];
    const float* gk  = (const float*)d_in[2];
    const float* Wsq = (const float*)d_in[3];
    const float* bsq = (const float*)d_in[4];
    const float* Wsk = (const float*)d_in[5];
    const float* bsk = (const float*)d_in[6];
    const float* Wq  = (const float*)d_in[7];
    const float* bq  = (const float*)d_in[8];
    const float* Wk  = (const float*)d_in[9];
    const float* bk  = (const float*)d_in[10];
    const float* Wv  = (const float*)d_in[11];
    const float* bv  = (const float*)d_in[12];
    const float* Wp  = (const float*)d_in[13];
    const float* bp  = (const float*)d_in[14];
    float* out = (float*)d_out;

    void *wh, *ball, *wph, *xh, *gh;
    cudaGetSymbolAddress(&wh,   g_wh);
    cudaGetSymbolAddress(&ball, g_ball);
    cudaGetSymbolAddress(&wph,  g_wph);
    cudaGetSymbolAddress(&xh,   g_xh);
    cudaGetSymbolAddress(&gh,   g_gh);

    assemble_kernel<<<MTOT + C_, 256>>>(Wq, bq, Wk, bk, Wv, bv, Wsq, bsq, Wsk, bsk, Wp);
    xcvt_kernel<<<(B_ * C_ * N_) / 1024, 256>>>(x);

    {   // gemm1: projection + ungated q/k/v bf16 + gate softmax tile (y=6 -> m0=768)
        dim3 g(N_ / 128, 7, B_);
        gemmh_kernel<1><<<g, 256>>>((const __half*)wh, (const float*)ball,
                                    (const __half*)xh, nullptr,
                                    MTOT, (long)C_ * N_, 0, gq, gk);
    }

    {   // attention (gates folded into softmax) + blend -> fp16 gated
        dim3 g(N_ / 128, NH, B_);
        attn_kernel<<<g, 256>>>();
    }

    {   // gemm2: out = Wp @ gated
        dim3 g(N_ / 128, C_ / 128, B_);
        gemmh_kernel<0><<<g, 256>>>((const __half*)wph, bp,
                                    (const __half*)gh, out,
                                    C_, (long)C_ * N_, (long)C_ * N_, nullptr, nullptr);
    }
}

// round 15
// speedup vs baseline: 1.1123x; 1.0052x over previous
#include <cuda_runtime.h>
#include <cuda_bf16.h>
#include <cuda_fp16.h>
#include <cstdint>

#define B_    8
#define C_    256
#define N_    1024
#define NH    8
#define HD    32
#define R_    4
#define MTOT  776
#define PR_   768
#define SCALE 0.17677669529663689f
#define LOG2E 1.4426950408889634f

// ---------------- scratch ----------------
__device__ float g_vf[B_ * C_ * N_];          // v projection fp32 (shortcut blend)
__device__ float g_sq[B_ * N_];
__device__ float g_sk[B_ * N_];
__device__ float g_ball[MTOT];
__device__ __half g_wh[MTOT * C_];            // stacked W (fp16): q,k,v,gq,gk rows
__device__ __half g_wph[C_ * C_];             // Wp (fp16)
__device__ __half g_xh[B_ * C_ * N_];         // x (fp16)
__device__ __nv_bfloat16 g_qB[B_ * C_ * N_];  // UNGATED q (bf16)
__device__ __nv_bfloat16 g_kB[B_ * C_ * N_];  // UNGATED k (bf16)
__device__ __nv_bfloat16 g_vB[B_ * C_ * N_];
__device__ __half g_gh[B_ * C_ * N_];         // gated output (fp16, gemm2 input)

// ---------------- ptx helpers ----------------
__device__ __forceinline__ void cp16(void* d, const void* s) {
    uint32_t ds = (uint32_t)__cvta_generic_to_shared(d);
    asm volatile("cp.async.cg.shared.global [%0], [%1], 16;" :: "r"(ds), "l"(s));
}
__device__ __forceinline__ void cp_commit() { asm volatile("cp.async.commit_group;"); }

__device__ __forceinline__ void ldsm_x4(uint32_t (&r)[4], const void* p) {
    uint32_t a = (uint32_t)__cvta_generic_to_shared(p);
    asm volatile("ldmatrix.sync.aligned.m8n8.x4.shared.b16 {%0,%1,%2,%3},[%4];"
                 : "=r"(r[0]), "=r"(r[1]), "=r"(r[2]), "=r"(r[3]) : "r"(a));
}
__device__ __forceinline__ void ldsm_x4t(uint32_t (&r)[4], const void* p) {
    uint32_t a = (uint32_t)__cvta_generic_to_shared(p);
    asm volatile("ldmatrix.sync.aligned.m8n8.x4.trans.shared.b16 {%0,%1,%2,%3},[%4];"
                 : "=r"(r[0]), "=r"(r[1]), "=r"(r[2]), "=r"(r[3]) : "r"(a));
}
__device__ __forceinline__ void ldsm_x2t(uint32_t (&r)[2], const void* p) {
    uint32_t a = (uint32_t)__cvta_generic_to_shared(p);
    asm volatile("ldmatrix.sync.aligned.m8n8.x2.trans.shared.b16 {%0,%1},[%2];"
                 : "=r"(r[0]), "=r"(r[1]) : "r"(a));
}
__device__ __forceinline__ void mma16816(float (&d)[4], const uint32_t (&a)[4], const uint32_t (&b)[2]) {
    asm volatile(
        "mma.sync.aligned.m16n8k16.row.col.f32.bf16.bf16.f32 "
        "{%0,%1,%2,%3},{%4,%5,%6,%7},{%8,%9},{%0,%1,%2,%3};"
        : "+f"(d[0]), "+f"(d[1]), "+f"(d[2]), "+f"(d[3])
        : "r"(a[0]), "r"(a[1]), "r"(a[2]), "r"(a[3]), "r"(b[0]), "r"(b[1]));
}
__device__ __forceinline__ void mma16816b(float (&d)[4], const uint32_t (&a)[4], uint32_t b0, uint32_t b1) {
    asm volatile(
        "mma.sync.aligned.m16n8k16.row.col.f32.bf16.bf16.f32 "
        "{%0,%1,%2,%3},{%4,%5,%6,%7},{%8,%9},{%0,%1,%2,%3};"
        : "+f"(d[0]), "+f"(d[1]), "+f"(d[2]), "+f"(d[3])
        : "r"(a[0]), "r"(a[1]), "r"(a[2]), "r"(a[3]), "r"(b0), "r"(b1));
}
__device__ __forceinline__ void mmah16816(float (&d)[4], const uint32_t (&a)[4], const uint32_t (&b)[2]) {
    asm volatile(
        "mma.sync.aligned.m16n8k16.row.col.f32.f16.f16.f32 "
        "{%0,%1,%2,%3},{%4,%5,%6,%7},{%8,%9},{%0,%1,%2,%3};"
        : "+f"(d[0]), "+f"(d[1]), "+f"(d[2]), "+f"(d[3])
        : "r"(a[0]), "r"(a[1]), "r"(a[2]), "r"(a[3]), "r"(b[0]), "r"(b[1]));
}
__device__ __forceinline__ uint32_t packbf(float lo, float hi) {
    __nv_bfloat162 t = __floats2bfloat162_rn(lo, hi);
    return *reinterpret_cast<uint32_t*>(&t);
}
__device__ __forceinline__ float2 bf2f2(uint32_t u) {
    __nv_bfloat162 t = *reinterpret_cast<__nv_bfloat162*>(&u);
    return __bfloat1622float2(t);
}
__device__ __forceinline__ uint32_t cvt2bf(float hi, float lo) {
    uint32_t y; asm("cvt.rn.bf16x2.f32 %0, %1, %2;" : "=r"(y) : "f"(hi), "f"(lo)); return y;
}
__device__ __forceinline__ uint32_t ex2_bf16x2(uint32_t x) {
    uint32_t y; asm("ex2.approx.ftz.bf16x2 %0, %1;" : "=r"(y) : "r"(x)); return y;
}

// ---------------- assemble weights -> fp16 ----------------
__global__ void assemble_kernel(
    const float* __restrict__ Wq, const float* __restrict__ bq,
    const float* __restrict__ Wk, const float* __restrict__ bk,
    const float* __restrict__ Wv, const float* __restrict__ bv,
    const float* __restrict__ Wsq, const float* __restrict__ bsq,
    const float* __restrict__ Wsk, const float* __restrict__ bsk,
    const float* __restrict__ Wp)
{
    int o = blockIdx.x;
    int k = threadIdx.x;
    if (o < MTOT) {
        const float* src; const float* bs; int r;
        if (o < 256)      { src = Wq  + o * 256;       bs = bq;  r = o; }
        else if (o < 512) { src = Wk  + (o-256) * 256; bs = bk;  r = o - 256; }
        else if (o < 768) { src = Wv  + (o-512) * 256; bs = bv;  r = o - 512; }
        else if (o < 772) { src = Wsq + (o-768) * 256; bs = bsq; r = o - 768; }
        else              { src = Wsk + (o-772) * 256; bs = bsk; r = o - 772; }
        g_wh[o * 256 + k] = __float2half_rn(src[k]);
        if (k == 0) g_ball[o] = bs[r];
    } else {
        int r = o - MTOT;
        g_wph[r * 256 + k] = __float2half_rn(Wp[r * 256 + k]);
    }
}

// ---------------- x -> fp16 (float4) ----------------
__global__ void xcvt_kernel(const float* __restrict__ x) {
    int i = (blockIdx.x * 256 + threadIdx.x) * 4;
    float4 v = *reinterpret_cast<const float4*>(x + i);
    __half2 p0 = __floats2half2_rn(v.x, v.y);
    __half2 p1 = __floats2half2_rn(v.z, v.w);
    uint2 o;
    o.x = *reinterpret_cast<uint32_t*>(&p0);
    o.y = *reinterpret_cast<uint32_t*>(&p1);
    *reinterpret_cast<uint2*>(g_xh + i) = o;
}

// ---------------- fp16 GEMM, BK=32, templated epilogue ----------------
// MODE 0: plain fp32 Y write (gemm2)
// MODE 1: gemm1 — q/k/v ungated bf16 write; m0==768 tile does gate softmax
#define ASTR 40
template<int MODE>
__global__ __launch_bounds__(256) void gemmh_kernel(
    const __half* __restrict__ W, const float* __restrict__ bias,
    const __half* __restrict__ X, float* __restrict__ Y,
    int Ma, long xStride, long yStride,
    const float* __restrict__ gq, const float* __restrict__ gk)
{
    int b  = blockIdx.z;
    int m0 = blockIdx.y * 128;
    int n0 = blockIdx.x * 128;
    const __half* XB = X + (long)b * xStride;

    __shared__ __align__(16) __half sA[2][128 * ASTR];
    __shared__ __align__(16) __half sB[2][32 * 136];
    __shared__ float sg[8][132];

    int tid  = threadIdx.x;
    int warp = tid >> 5, lane = tid & 31;
    int wm = warp >> 2, wn = warp & 3;
    int g = lane >> 2, t = lane & 3;

    float acc[4][4][4];
    #pragma unroll
    for (int mi = 0; mi < 4; mi++)
        #pragma unroll
        for (int ni = 0; ni < 4; ni++)
            #pragma unroll
            for (int r = 0; r < 4; r++) acc[mi][ni][r] = 0.f;

    auto loadStage = [&](int step, int s) {
        int k0 = step * 32;
        #pragma unroll
        for (int c = 0; c < 2; c++) {
            int idx = tid + c * 256;
            int row = idx >> 2, quarter = idx & 3;
            int gm = m0 + row;
            __half* d = &sA[s][row * ASTR + quarter * 8];
            if (gm < Ma) cp16(d, W + gm * 256 + k0 + quarter * 8);
            else         *reinterpret_cast<uint4*>(d) = make_uint4(0,0,0,0);
        }
        #pragma unroll
        for (int c = 0; c < 2; c++) {
            int idx = tid + c * 256;
            int row = idx >> 4, seg = idx & 15;
            cp16(&sB[s][row * 136 + seg * 8], XB + (long)(k0 + row) * N_ + n0 + seg * 8);
        }
        cp_commit();
    };

    loadStage(0, 0);
    for (int step = 0; step < 8; step++) {
        int s = step & 1;
        if (step < 7) {
            loadStage(step + 1, s ^ 1);
            asm volatile("cp.async.wait_group 1;");
        } else {
            asm volatile("cp.async.wait_group 0;");
        }
        __syncthreads();

        uint32_t afr[2][4][4];
        #pragma unroll
        for (int ku = 0; ku < 2; ku++)
            #pragma unroll
            for (int mi = 0; mi < 4; mi++) {
                const __half* p = &sA[s][(wm * 64 + mi * 16 + (lane & 15)) * ASTR + ku * 16] + ((lane >> 4) & 1) * 8;
                ldsm_x4(afr[ku][mi], p);
            }
        uint32_t bfr[2][4][2];
        #pragma unroll
        for (int ku = 0; ku < 2; ku++)
            #pragma unroll
            for (int ni = 0; ni < 4; ni++) {
                const __half* p = &sB[s][(ku * 16 + (lane & 15)) * 136 + wn * 32 + ni * 8];
                ldsm_x2t(bfr[ku][ni], p);
            }
        #pragma unroll
        for (int mi = 0; mi < 4; mi++)
            #pragma unroll
            for (int ni = 0; ni < 4; ni++) {
                mmah16816(acc[mi][ni], afr[0][mi], bfr[0][ni]);
                mmah16816(acc[mi][ni], afr[1][mi], bfr[1][ni]);
            }
        __syncthreads();
    }

    if (MODE == 0) {
        float* Yb = Y + (long)b * yStride;
        #pragma unroll
        for (int mi = 0; mi < 4; mi++) {
            int r0 = m0 + wm * 64 + mi * 16 + g;
            int r1 = r0 + 8;
            float bv0 = bias[r0], bv1 = bias[r1];
            #pragma unroll
            for (int ni = 0; ni < 4; ni++) {
                int col = n0 + wn * 32 + ni * 8 + 2 * t;
                Yb[(long)r0 * N_ + col]     = acc[mi][ni][0] + bv0;
                Yb[(long)r0 * N_ + col + 1] = acc[mi][ni][1] + bv0;
                Yb[(long)r1 * N_ + col]     = acc[mi][ni][2] + bv1;
                Yb[(long)r1 * N_ + col + 1] = acc[mi][ni][3] + bv1;
            }
        }
    } else {
        if (m0 < PR_) {
            int cat = m0 >> 8;
            __nv_bfloat16* dst = (cat == 0) ? g_qB : (cat == 1) ? g_kB : g_vB;
            #pragma unroll
            for (int mi = 0; mi < 4; mi++) {
                int gr0 = m0 + wm * 64 + mi * 16 + g;
                int rr0 = gr0 & 255, rr1 = rr0 + 8;
                float bv0 = bias[gr0], bv1 = bias[gr0 + 8];
                long o0 = ((long)b * C_ + rr0) * N_;
                long o1 = ((long)b * C_ + rr1) * N_;
                #pragma unroll
                for (int ni = 0; ni < 4; ni++) {
                    int col = n0 + wn * 32 + ni * 8 + 2 * t;
                    float a0 = acc[mi][ni][0] + bv0, a1 = acc[mi][ni][1] + bv0;
                    float a2 = acc[mi][ni][2] + bv1, a3 = acc[mi][ni][3] + bv1;
                    *reinterpret_cast<uint32_t*>(dst + o0 + col) = packbf(a0, a1);
                    *reinterpret_cast<uint32_t*>(dst + o1 + col) = packbf(a2, a3);
                    if (cat == 2) {
                        *reinterpret_cast<float2*>(g_vf + o0 + col) = make_float2(a0, a1);
                        *reinterpret_cast<float2*>(g_vf + o1 + col) = make_float2(a2, a3);
                    }
                }
            }
        } else {
            if (wm == 0) {
                float bv = bias[768 + g];
                #pragma unroll
                for (int ni = 0; ni < 4; ni++) {
                    int col = wn * 32 + ni * 8 + 2 * t;
                    sg[g][col]     = acc[0][ni][0] + bv;
                    sg[g][col + 1] = acc[0][ni][1] + bv;
                }
            }
            __syncthreads();
            if (tid < 128) {
                int n = n0 + tid;
                float lq[4], lk[4];
                #pragma unroll
                for (int r = 0; r < 4; r++) {
                    lq[r] = sg[r][tid]     + gq[(b * R_ + r) * N_ + n];
                    lk[r] = sg[4 + r][tid] + gk[(b * R_ + r) * N_ + n];
                }
                float mq = fmaxf(fmaxf(lq[0], lq[1]), fmaxf(lq[2], lq[3]));
                float s2 = 0.f;
                #pragma unroll
                for (int r = 0; r < 4; r++) s2 += __expf(lq[r] - mq);
                g_sq[b * N_ + n] = __expf(lq[0] - mq) / s2;
                float mk = fmaxf(fmaxf(lk[0], lk[1]), fmaxf(lk[2], lk[3]));
                s2 = 0.f;
                #pragma unroll
                for (int r = 0; r < 4; r++) s2 += __expf(lk[r] - mk);
                g_sk[b * N_ + n] = __expf(lk[0] - mk) / s2;
            }
        }
    }
}

// ---------------- flash attention: gated Q at load, x4 ldsm, sk in softmax ----------------
#define QSTR 136
#define KSTR 72
__global__ __launch_bounds__(256) void attn_kernel() {
    int b = blockIdx.z, h = blockIdx.y;
    int n0 = blockIdx.x * 128;
    const __nv_bfloat16* qBp = g_qB + ((long)b * C_ + h * HD) * N_;
    const __nv_bfloat16* kBp = g_kB + ((long)b * C_ + h * HD) * N_;
    const __nv_bfloat16* vBp = g_vB + ((long)b * C_ + h * HD) * N_;

    __shared__ __align__(16) __nv_bfloat16 qsm[32 * QSTR];
    __shared__ __align__(16) __nv_bfloat16 ksm[2][32 * KSTR];
    __shared__ __align__(16) __nv_bfloat16 vsm[2][32 * KSTR];
    __shared__ float ssk[N_];
    __shared__ float osm[32][130];

    int tid = threadIdx.x;
    int w = tid >> 5, lane = tid & 31;
    int g = lane >> 2, t = lane & 3;

    auto loadKV = [&](int m0, int s) {
        int row = tid >> 3, seg = tid & 7;
        cp16(&ksm[s][row * KSTR + seg * 8], kBp + (long)row * N_ + m0 + seg * 8);
        cp16(&vsm[s][row * KSTR + seg * 8], vBp + (long)row * N_ + m0 + seg * 8);
        cp_commit();
    };

    loadKV(0, 0);

    // preload sk + gated Q tile (fold sq*QMUL into Q at load)
    *reinterpret_cast<float4*>(ssk + tid * 4) =
        *reinterpret_cast<const float4*>(g_sk + (long)b * N_ + tid * 4);
    const float QMUL = SCALE * LOG2E;
    #pragma unroll
    for (int c = tid; c < 512; c += 256) {
        int row = c >> 4, seg = c & 15;
        uint4 raw = *reinterpret_cast<const uint4*>(qBp + (long)row * N_ + n0 + seg * 8);
        float4 s0 = *reinterpret_cast<const float4*>(g_sq + (long)b * N_ + n0 + seg * 8);
        float4 s1 = *reinterpret_cast<const float4*>(g_sq + (long)b * N_ + n0 + seg * 8 + 4);
        float2 v0 = bf2f2(raw.x), v1 = bf2f2(raw.y), v2 = bf2f2(raw.z), v3 = bf2f2(raw.w);
        uint4 outq;
        outq.x = packbf(v0.x * s0.x * QMUL, v0.y * s0.y * QMUL);
        outq.y = packbf(v1.x * s0.z * QMUL, v1.y * s0.w * QMUL);
        outq.z = packbf(v2.x * s1.x * QMUL, v2.y * s1.y * QMUL);
        outq.w = packbf(v3.x * s1.z * QMUL, v3.y * s1.w * QMUL);
        *reinterpret_cast<uint4*>(qsm + row * QSTR + seg * 8) = outq;
    }
    __syncthreads();

    uint32_t aq[2][4];
    #pragma unroll
    for (int ku = 0; ku < 2; ku++) {
        int d = ku * 16 + ((lane >> 4) & 1) * 8 + (lane & 7);
        int col = w * 16 + ((lane >> 3) & 1) * 8;
        ldsm_x4t(aq[ku], qsm + d * QSTR + col);
    }

    float oacc[4][4];
    #pragma unroll
    for (int nd = 0; nd < 4; nd++)
        #pragma unroll
        for (int r = 0; r < 4; r++) oacc[nd][r] = 0.f;
    float lacc[4] = {0.f, 0.f, 0.f, 0.f};
    uint32_t bones[2];
    bones[0] = 0x3F803F80u; bones[1] = 0x3F803F80u;

    for (int it = 0; it < 16; it++) {
        int s = it & 1;
        if (it < 15) {
            loadKV((it + 1) * 64, s ^ 1);
            asm volatile("cp.async.wait_group 1;");
        } else {
            asm volatile("cp.async.wait_group 0;");
        }
        __syncthreads();

        // S = Q^T K — K frags fetched in pairs via x4t
        float sS[8][4];
        #pragma unroll
        for (int np = 0; np < 4; np++) {
            #pragma unroll
            for (int r = 0; r < 4; r++) { sS[2*np][r] = 0.f; sS[2*np+1][r] = 0.f; }
            #pragma unroll
            for (int ku = 0; ku < 2; ku++) {
                uint32_t bk[4];
                ldsm_x4t(bk, &ksm[s][(ku * 16 + (lane & 15)) * KSTR + np * 16 + ((lane >> 4) & 1) * 8]);
                mma16816b(sS[2*np],   aq[ku], bk[0], bk[1]);
                mma16816b(sS[2*np+1], aq[ku], bk[2], bk[3]);
            }
        }

        // gate: S *= sk_col (q gate pre-folded), then P = 2^S
        int km = it * 64;
        #pragma unroll
        for (int ni = 0; ni < 8; ni++) {
            float2 skp = *reinterpret_cast<const float2*>(ssk + km + ni * 8 + 2 * t);
            sS[ni][0] *= skp.x;
            sS[ni][1] *= skp.y;
            sS[ni][2] *= skp.x;
            sS[ni][3] *= skp.y;
        }

        #pragma unroll
        for (int u = 0; u < 4; u++) {
            uint32_t ap[4];
            ap[0] = ex2_bf16x2(cvt2bf(sS[2*u][1],   sS[2*u][0]));
            ap[1] = ex2_bf16x2(cvt2bf(sS[2*u][3],   sS[2*u][2]));
            ap[2] = ex2_bf16x2(cvt2bf(sS[2*u+1][1], sS[2*u+1][0]));
            ap[3] = ex2_bf16x2(cvt2bf(sS[2*u+1][3], sS[2*u+1][2]));
            mma16816(lacc, ap, bones);
            // V frags fetched in pairs via x4
            #pragma unroll
            for (int ndp = 0; ndp < 2; ndp++) {
                uint32_t bv[4];
                ldsm_x4(bv, &vsm[s][((ndp * 2 + ((lane >> 4) & 1)) * 8 + (lane & 7)) * KSTR + u * 16 + ((lane >> 3) & 1) * 8]);
                mma16816b(oacc[ndp*2],   ap, bv[0], bv[1]);
                mma16816b(oacc[ndp*2+1], ap, bv[2], bv[3]);
            }
        }
        __syncthreads();
    }

    float inv0 = 1.f / lacc[0], inv1 = 1.f / lacc[2];

    #pragma unroll
    for (int nd = 0; nd < 4; nd++) {
        osm[nd * 8 + 2 * t][w * 16 + g]         = oacc[nd][0] * inv0;
        osm[nd * 8 + 2 * t + 1][w * 16 + g]     = oacc[nd][1] * inv0;
        osm[nd * 8 + 2 * t][w * 16 + g + 8]     = oacc[nd][2] * inv1;
        osm[nd * 8 + 2 * t + 1][w * 16 + g + 8] = oacc[nd][3] * inv1;
    }
    __syncthreads();

    const float* vfull = g_vf + ((long)b * C_ + h * HD) * N_ + n0;
    int n = tid & 127;
    float sqv = g_sq[(long)b * N_ + n0 + n];
    #pragma unroll
    for (int d = tid >> 7; d < HD; d += 2) {
        float gated = sqv * osm[d][n] + (1.f - sqv) * vfull[(long)d * N_ + n];
        g_gh[((long)b * C_ + h * HD + d) * N_ + n0 + n] = __float2half_rn(gated);
    }
}

// ---------------- launch ----------------
extern "C" void kernel_launch(void* const* d_in, const int* in_sizes, int n_in,
                              void* d_out, int out_size) {
    const float* x   = (const float*)d_in[0];
    const float* gq  = (const float*)d_in[1];
    const float* gk  = (const float*)d_in[2];
    const float* Wsq = (const float*)d_in[3];
    const float* bsq = (const float*)d_in[4];
    const float* Wsk = (const float*)d_in[5];
    const float* bsk = (const float*)d_in[6];
    const float* Wq  = (const float*)d_in[7];
    const float* bq  = (const float*)d_in[8];
    const float* Wk  = (const float*)d_in[9];
    const float* bk  = (const float*)d_in[10];
    const float* Wv  = (const float*)d_in[11];
    const float* bv  = (const float*)d_in[12];
    const float* Wp  = (const float*)d_in[13];
    const float* bp  = (const float*)d_in[14];
    float* out = (float*)d_out;

    void *wh, *ball, *wph, *xh, *gh;
    cudaGetSymbolAddress(&wh,   g_wh);
    cudaGetSymbolAddress(&ball, g_ball);
    cudaGetSymbolAddress(&wph,  g_wph);
    cudaGetSymbolAddress(&xh,   g_xh);
    cudaGetSymbolAddress(&gh,   g_gh);

    assemble_kernel<<<MTOT + C_, 256>>>(Wq, bq, Wk, bk, Wv, bv, Wsq, bsq, Wsk, bsk, Wp);
    xcvt_kernel<<<(B_ * C_ * N_) / 1024, 256>>>(x);

    {   // gemm1: projection + ungated q/k/v bf16 + gate softmax tile
        dim3 g(N_ / 128, 7, B_);
        gemmh_kernel<1><<<g, 256>>>((const __half*)wh, (const float*)ball,
                                    (const __half*)xh, nullptr,
                                    MTOT, (long)C_ * N_, 0, gq, gk);
    }

    {   // attention (gates folded) + blend -> fp16 gated
        dim3 g(N_ / 128, NH, B_);
        attn_kernel<<<g, 256>>>();
    }

    {   // gemm2: out = Wp @ gated
        dim3 g(N_ / 128, C_ / 128, B_);
        gemmh_kernel<0><<<g, 256>>>((const __half*)wph, bp,
                                    (const __half*)gh, out,
                                    C_, (long)C_ * N_, (long)C_ * N_, nullptr, nullptr);
    }
}